// round 15
// baseline (speedup 1.0000x reference)
#include <cuda_runtime.h>
#include <cuda_fp16.h>
#include <cstdint>
#include <math.h>

#define NCHUNK 77
#define SM_A    0
#define SM_W    40960
#define SM_MBAR 106496
#define SM_TOTAL 106624

__device__ __forceinline__ uint32_t smem_u32(const void* p){
    uint32_t a; asm("{ .reg .u64 t; cvta.to.shared.u64 t, %1; cvt.u32.u64 %0, t; }" : "=r"(a) : "l"(p)); return a;
}
#define MB_INIT(m,c) asm volatile("mbarrier.init.shared.b64 [%0], %1;" :: "r"(m), "r"((uint32_t)(c)) : "memory")
#define MB_EXTX(m,b) asm volatile("mbarrier.arrive.expect_tx.shared.b64 _, [%0], %1;" :: "r"(m), "r"((uint32_t)(b)) : "memory")
#define MB_ARR(m)    asm volatile("mbarrier.arrive.shared.b64 _, [%0];" :: "r"(m) : "memory")
#define MB_WAIT(m,ph) do{ uint32_t _m=(m),_p=(ph),_d; \
    asm volatile("{\n\t.reg .pred p;\n\tmbarrier.try_wait.parity.acquire.cta.shared::cta.b64 p, [%1], %2;\n\tselp.b32 %0,1,0,p;\n\t}" : "=r"(_d) : "r"(_m), "r"(_p) : "memory"); \
    if(!_d){ asm volatile("{\n\t.reg .pred P1;\n\tWL_%=:\n\tmbarrier.try_wait.parity.acquire.cta.shared::cta.b64 P1, [%0], %1, 0x989680;\n\t@P1 bra.uni WD_%=;\n\tbra.uni WL_%=;\n\tWD_%=:\n\t}" :: "r"(_m), "r"(_p) : "memory"); } }while(0)
__device__ __forceinline__ void bulk_g2s(uint32_t dst, const void* src, uint32_t bytes, uint32_t mbar){
    asm volatile("cp.async.bulk.shared::cluster.global.mbarrier::complete_tx::bytes [%0], [%1], %2, [%3];"
        :: "r"(dst), "l"(src), "r"(bytes), "r"(mbar) : "memory");
}
#define LDMX4(r,a) asm volatile("ldmatrix.sync.aligned.m8n8.x4.shared.b16 {%0,%1,%2,%3}, [%4];" \
    : "=r"((r)[0]),"=r"((r)[1]),"=r"((r)[2]),"=r"((r)[3]) : "r"(a))
#define MMA16816(c,a,b0,b1) asm volatile( \
    "mma.sync.aligned.m16n8k16.row.col.f32.f16.f16.f32 {%0,%1,%2,%3},{%4,%5,%6,%7},{%8,%9},{%0,%1,%2,%3};" \
    : "+f"((c)[0]),"+f"((c)[1]),"+f"((c)[2]),"+f"((c)[3]) \
    : "r"((a)[0]),"r"((a)[1]),"r"((a)[2]),"r"((a)[3]), "r"(b0),"r"(b1))
#define BAR_GRP(id) asm volatile("bar.sync %0, 128;" :: "r"(id) : "memory")

__device__ __forceinline__ uint32_t packh2(float v0, float v1){
    __half2 h = __floats2half2_rn(v0, v1);
    return *reinterpret_cast<uint32_t*>(&h);
}

// segment tables: 12 segments over 10 GEMM layers, k32 chunks
__constant__ unsigned char sg_layer[12]={0,1,2,3,4,5,5,6,7,8,9,9};
__constant__ short sg_cnt[12]={2,8,8,8,8,2,8,8,8,8,8,1};
__constant__ short sg_cum[12]={0,2,10,18,26,34,36,44,52,60,68,76};
__constant__ unsigned char sg_akt[12]={32,0,0,0,0,32,0,0,0,0,0,32};
__constant__ unsigned char sg_first[12]={1,1,1,1,1,1,0,1,1,1,1,0};
__constant__ unsigned char sg_end[12]={1,1,1,1,1,0,1,1,1,1,0,1};
__constant__ unsigned char sg_w[12]={0,1,2,3,4,5,5,6,7,8,9,9};
__constant__ short sg_wcol[12]={0,0,0,0,0,0,63,0,0,0,0,256};
__constant__ short sg_kmax[12]={63,256,256,256,256,63,256,256,256,256,256,27};
__constant__ short sg_wstr[12]={63,256,256,256,256,319,319,256,256,256,283,283};
__constant__ short sg_nval[12]={256,256,256,256,256,256,256,256,256,256,128,128};

__device__ __align__(1024) unsigned char g_ws[NCHUNK*16384];

struct PrepParams { const float* w[10]; };
__global__ void prep(PrepParams pp){
    int c = blockIdx.x, s = 11;
    for (int i = 1; i < 12; i++) if (c < sg_cum[i]){ s = i-1; break; }
    int ci = c - sg_cum[s];
    const float* W = pp.w[sg_w[s]];
    int kval = sg_kmax[s] - 32*ci; if (kval > 32) kval = 32;
    int nval = sg_nval[s], ws = sg_wstr[s], col0 = sg_wcol[s] + ci*32;
    unsigned char* dst = g_ws + (long long)c*16384;
    for (int idx = threadIdx.x; idx < 8192; idx += blockDim.x){
        int n = idx>>5, kk = idx&31;
        float w = (kk < kval && n < nval) ? W[n*ws + col0 + kk] : 0.f;
        uint32_t off = (uint32_t)((((n>>3)*4 + (kk>>3))<<7) + ((n&7)<<4) + ((kk&7)<<1));
        *(__half*)(dst+off) = __float2half_rn(w);
    }
}

struct MainParams {
    const float* pts; const float* dirs;
    const float* bias[10];           // bb0..7, brm, br0
    const float* Wsig; const float* bsig;
    const float* Wr1;  const float* br1;
    float* out; int N;
};

__device__ __forceinline__ float embed_val(const float* base, int g0, int m, int k){
    if (k < 3) return base[(g0+m)*3+k];
    int q = k-3, f = q/6, rr = q - f*6, d = rr%3;
    float x = base[(g0+m)*3+d] * (float)(1<<f);
    return (rr < 3) ? sinf(x) : cosf(x);
}
__device__ __forceinline__ void store_a(unsigned char* smem, int m, int col, float v){
    uint32_t off = (uint32_t)((((m>>3)*40 + (col>>3))<<7) + (m&7)*16 + (col&7)*2);
    *(__half*)(smem+SM_A+off) = __float2half_rn(v);
}
__device__ __forceinline__ float read_a(const unsigned char* smem, int m, int k){
    uint32_t off = (uint32_t)((((m>>3)*40 + (k>>3))<<7) + (m&7)*16 + (k&7)*2);
    return __half2float(*(const __half*)(smem+SM_A+off));
}

__global__ void __launch_bounds__(256,2) nerf_mma(MainParams P)
{
    extern __shared__ __align__(1024) unsigned char smem[];
    const uint32_t sb = smem_u32(smem), mb = sb + SM_MBAR;
    const int tid = threadIdx.x, lane = tid&31, wid = tid>>5;
    const int ms = wid&1, ns = wid>>1;       // 2 m-groups x 4 n-blocks
    const int gtid = (wid>>1)*32 + lane;     // 0..127 within ms-group
    const int gp0 = blockIdx.x*64;
    const long long N = P.N;

    const uint32_t abase = sb + SM_A +
        (uint32_t)(((ms*4 + ((lane>>3)&1))*40 + (lane>>4))*128 + (lane&7)*16);
    const uint32_t bbase =
        (uint32_t)((ns*8 + (lane>>4))*512 + ((lane>>3)&1)*128 + (lane&7)*16);

    if (tid == 0){
        MB_INIT(mb,1); MB_INIT(mb+8,1); MB_INIT(mb+16,1); MB_INIT(mb+24,1);
        MB_INIT(mb+32,8); MB_INIT(mb+40,8); MB_INIT(mb+48,8); MB_INIT(mb+56,8);
    }
    __syncthreads();
    if (tid == 0){
        #pragma unroll
        for (int b = 0; b < 4; b++){
            MB_EXTX(mb + 8*b, 16384);
            bulk_g2s(sb + SM_W + b*16384, g_ws + (long long)b*16384, 16384, mb + 8*b);
        }
    }
    for (int i = tid*16; i < 40960; i += 256*16) *(uint4*)(smem+i) = make_uint4(0,0,0,0);
    __syncthreads();
    for (int idx = tid; idx < 64*63; idx += 256){
        int m = idx/63, k = idx - m*63;
        store_a(smem, m, 256+k, embed_val(P.pts, gp0, m, k));
    }
    {
        float* outD = P.out + 4*N;
        for (int idx = tid; idx < 64*27; idx += 256){
            int m = idx/27, k = idx - m*27;
            outD[(long long)(gp0+m)*27 + k] = embed_val(P.dirs, gp0, m, k);
        }
    }
    __syncthreads();

    float acc[64];
    int c = 0; uint32_t phs = 0, cphs = 0;
    #pragma unroll 1
    for (int s = 0; s < 12; s++){
        const int cnt = sg_cnt[s], layer = sg_layer[s];
        const bool act = (sg_nval[s] == 256) || (ns < 2);
        uint32_t koff = (uint32_t)sg_akt[s] * 128;
        if (sg_first[s]){
            #pragma unroll
            for (int i = 0; i < 64; i++) acc[i] = 0.f;
        }
        #pragma unroll 1
        for (int ci = 0; ci < cnt; ci++, c++){
            int buf = c & 3;
            MB_WAIT(mb + 8*buf, (phs>>buf)&1);
            phs ^= 1u << buf;
            if (act){
                const uint32_t ka = abase + koff;
                const uint32_t wbb = sb + SM_W + buf*16384 + bbase;
                uint32_t af[4][4];
                #pragma unroll
                for (int kh = 0; kh < 2; kh++)
                    #pragma unroll
                    for (int mh = 0; mh < 2; mh++)
                        LDMX4(af[kh*2+mh], ka + kh*256 + mh*10240);
                #pragma unroll
                for (int kh = 0; kh < 2; kh++)
                    #pragma unroll
                    for (int g = 0; g < 4; g++){
                        uint32_t bh[4];
                        LDMX4(bh, wbb + g*1024 + kh*256);
                        MMA16816(acc + ((g*2+0)*2+0)*4, af[kh*2+0], bh[0], bh[1]);
                        MMA16816(acc + ((g*2+0)*2+1)*4, af[kh*2+1], bh[0], bh[1]);
                        MMA16816(acc + ((g*2+1)*2+0)*4, af[kh*2+0], bh[2], bh[3]);
                        MMA16816(acc + ((g*2+1)*2+1)*4, af[kh*2+1], bh[2], bh[3]);
                    }
            }
            koff += 512;
            if (lane == 0) MB_ARR(mb + 32 + 8*buf);
            if (tid == 0 && c+4 < NCHUNK){
                MB_WAIT(mb + 32 + 8*buf, (cphs>>buf)&1);
                cphs ^= 1u << buf;
                MB_EXTX(mb + 8*buf, 16384);
                bulk_g2s(sb + SM_W + buf*16384, g_ws + (long long)(c+4)*16384, 16384, mb + 8*buf);
            }
        }
        if (sg_end[s]){
            BAR_GRP(1 + ms);   // group done reading A for this layer
            const float* bp = P.bias[layer];
            const int nmax = (layer == 9) ? 128 : 256;
            if (act){
                #pragma unroll
                for (int nti = 0; nti < 8; nti++)
                    #pragma unroll
                    for (int mh = 0; mh < 2; mh++){
                        float* a4 = acc + (nti*2 + mh)*4;
                        int n0 = ns*64 + nti*8 + (lane&3)*2;
                        int mr = ms*32 + mh*16 + (lane>>2);
                        float b0 = (n0 < nmax) ? __ldg(bp + n0) : 0.f;
                        float b1 = (n0+1 < nmax) ? __ldg(bp + n0 + 1) : 0.f;
                        int ktw = ns*8 + nti;
                        float v0 = fmaxf(a4[0]+b0,0.f), v1 = fmaxf(a4[1]+b1,0.f);
                        float v2 = fmaxf(a4[2]+b0,0.f), v3 = fmaxf(a4[3]+b1,0.f);
                        uint32_t o0 = (uint32_t)((((mr>>3)*40 + ktw)<<7) + (mr&7)*16 + (lane&3)*4);
                        int m2 = mr + 8;
                        uint32_t o1 = (uint32_t)((((m2>>3)*40 + ktw)<<7) + (m2&7)*16 + (lane&3)*4);
                        *(uint32_t*)(smem+SM_A+o0) = packh2(v0, v1);
                        *(uint32_t*)(smem+SM_A+o1) = packh2(v2, v3);
                    }
            }
            if (layer == 5){
                // group-local De store into A cols 256.. (rows of own ms half)
                for (int i = gtid; i < 32*27; i += 128){
                    int mloc = i/27, k = i - mloc*27;
                    int m = ms*32 + mloc;
                    store_a(smem, m, 256+k, embed_val(P.dirs, gp0, m, k));
                }
            }
            BAR_GRP(1 + ms);   // group writes visible
            if (layer == 7){
                // sigma: 8 m-rows per warp (own group), 4 lanes split k
                int m = ms*32 + (wid>>1)*8 + (lane>>2);
                int k0 = lane&3;
                float ssum = 0.f;
                #pragma unroll 16
                for (int k = k0; k < 256; k += 4)
                    ssum = fmaf(read_a(smem, m, k), __ldg(P.Wsig + k), ssum);
                ssum += __shfl_xor_sync(0xffffffffu, ssum, 1);
                ssum += __shfl_xor_sync(0xffffffffu, ssum, 2);
                if (k0 == 0) P.out[3*N + gp0 + m] = ssum + __ldg(P.bsig);
            }
            if (layer == 9){
                int m = ms*32 + (wid>>1)*8 + (lane>>2);
                int k0 = lane&3;
                float r0 = 0.f, r1 = 0.f, r2 = 0.f;
                #pragma unroll 8
                for (int k = k0; k < 128; k += 4){
                    float av = read_a(smem, m, k);
                    r0 = fmaf(av, __ldg(P.Wr1 + k), r0);
                    r1 = fmaf(av, __ldg(P.Wr1 + 128 + k), r1);
                    r2 = fmaf(av, __ldg(P.Wr1 + 256 + k), r2);
                }
                r0 += __shfl_xor_sync(0xffffffffu, r0, 1); r0 += __shfl_xor_sync(0xffffffffu, r0, 2);
                r1 += __shfl_xor_sync(0xffffffffu, r1, 1); r1 += __shfl_xor_sync(0xffffffffu, r1, 2);
                r2 += __shfl_xor_sync(0xffffffffu, r2, 1); r2 += __shfl_xor_sync(0xffffffffu, r2, 2);
                if (k0 == 0){
                    long long gm = gp0 + m;
                    P.out[gm*3+0] = 1.f/(1.f + expf(-(r0 + __ldg(P.br1+0))));
                    P.out[gm*3+1] = 1.f/(1.f + expf(-(r1 + __ldg(P.br1+1))));
                    P.out[gm*3+2] = 1.f/(1.f + expf(-(r2 + __ldg(P.br1+2))));
                }
            }
        }
    }
}

extern "C" void kernel_launch(void* const* d_in, const int* in_sizes, int n_in,
                              void* d_out, int out_size)
{
    PrepParams pp;
    for (int i = 0; i < 8; i++) pp.w[i] = (const float*)d_in[2 + 2*i];
    pp.w[8] = (const float*)d_in[20];
    pp.w[9] = (const float*)d_in[22];

    MainParams mp;
    mp.pts  = (const float*)d_in[0];
    mp.dirs = (const float*)d_in[1];
    for (int i = 0; i < 8; i++) mp.bias[i] = (const float*)d_in[3 + 2*i];
    mp.bias[8] = (const float*)d_in[21];     // brm
    mp.bias[9] = (const float*)d_in[23];     // br0
    mp.Wsig = (const float*)d_in[18]; mp.bsig = (const float*)d_in[19];
    mp.Wr1  = (const float*)d_in[24]; mp.br1  = (const float*)d_in[25];
    mp.out  = (float*)d_out;
    mp.N    = in_sizes[0] / 3;

    prep<<<NCHUNK, 256>>>(pp);
    cudaFuncSetAttribute(nerf_mma, cudaFuncAttributeMaxDynamicSharedMemorySize, SM_TOTAL);
    nerf_mma<<<mp.N/64, 256, SM_TOTAL>>>(mp);
}

// round 16
// speedup vs baseline: 1.0558x; 1.0558x over previous
#include <cuda_runtime.h>
#include <cuda_fp16.h>
#include <cstdint>
#include <math.h>

#define NCHUNK 77
#define SM_A    0
#define SM_W    40960
#define SM_MBAR 106496
#define SM_TOTAL 106624

__device__ __forceinline__ uint32_t smem_u32(const void* p){
    uint32_t a; asm("{ .reg .u64 t; cvta.to.shared.u64 t, %1; cvt.u32.u64 %0, t; }" : "=r"(a) : "l"(p)); return a;
}
#define MB_INIT(m,c) asm volatile("mbarrier.init.shared.b64 [%0], %1;" :: "r"(m), "r"((uint32_t)(c)) : "memory")
#define MB_EXTX(m,b) asm volatile("mbarrier.arrive.expect_tx.shared.b64 _, [%0], %1;" :: "r"(m), "r"((uint32_t)(b)) : "memory")
#define MB_ARR(m)    asm volatile("mbarrier.arrive.shared.b64 _, [%0];" :: "r"(m) : "memory")
#define MB_WAIT(m,ph) do{ uint32_t _m=(m),_p=(ph),_d; \
    asm volatile("{\n\t.reg .pred p;\n\tmbarrier.try_wait.parity.acquire.cta.shared::cta.b64 p, [%1], %2;\n\tselp.b32 %0,1,0,p;\n\t}" : "=r"(_d) : "r"(_m), "r"(_p) : "memory"); \
    if(!_d){ asm volatile("{\n\t.reg .pred P1;\n\tWL_%=:\n\tmbarrier.try_wait.parity.acquire.cta.shared::cta.b64 P1, [%0], %1, 0x989680;\n\t@P1 bra.uni WD_%=;\n\tbra.uni WL_%=;\n\tWD_%=:\n\t}" :: "r"(_m), "r"(_p) : "memory"); } }while(0)
__device__ __forceinline__ void bulk_g2s(uint32_t dst, const void* src, uint32_t bytes, uint32_t mbar){
    asm volatile("cp.async.bulk.shared::cluster.global.mbarrier::complete_tx::bytes [%0], [%1], %2, [%3];"
        :: "r"(dst), "l"(src), "r"(bytes), "r"(mbar) : "memory");
}
#define LDMX4(r,a) asm volatile("ldmatrix.sync.aligned.m8n8.x4.shared.b16 {%0,%1,%2,%3}, [%4];" \
    : "=r"((r)[0]),"=r"((r)[1]),"=r"((r)[2]),"=r"((r)[3]) : "r"(a))
#define MMA16816(c,a,b0,b1) asm volatile( \
    "mma.sync.aligned.m16n8k16.row.col.f32.f16.f16.f32 {%0,%1,%2,%3},{%4,%5,%6,%7},{%8,%9},{%0,%1,%2,%3};" \
    : "+f"((c)[0]),"+f"((c)[1]),"+f"((c)[2]),"+f"((c)[3]) \
    : "r"((a)[0]),"r"((a)[1]),"r"((a)[2]),"r"((a)[3]), "r"(b0),"r"(b1))

// one B-group: 4 MMAs (g selects acc quads, kh selects A frags)
#define DOGRP(b, khh, g) \
    MMA16816(acc + (g)*16 + 0,  af[(khh)*2+0], (b)[0], (b)[1]); \
    MMA16816(acc + (g)*16 + 4,  af[(khh)*2+1], (b)[0], (b)[1]); \
    MMA16816(acc + (g)*16 + 8,  af[(khh)*2+0], (b)[2], (b)[3]); \
    MMA16816(acc + (g)*16 + 12, af[(khh)*2+1], (b)[2], (b)[3]);

__device__ __forceinline__ uint32_t packh2(float v0, float v1){
    __half2 h = __floats2half2_rn(v0, v1);
    return *reinterpret_cast<uint32_t*>(&h);
}

// segment tables: 12 segments over 10 GEMM layers, k32 chunks
__constant__ unsigned char sg_layer[12]={0,1,2,3,4,5,5,6,7,8,9,9};
__constant__ short sg_cnt[12]={2,8,8,8,8,2,8,8,8,8,8,1};
__constant__ short sg_cum[12]={0,2,10,18,26,34,36,44,52,60,68,76};
__constant__ unsigned char sg_akt[12]={32,0,0,0,0,32,0,0,0,0,0,32};
__constant__ unsigned char sg_first[12]={1,1,1,1,1,1,0,1,1,1,1,0};
__constant__ unsigned char sg_end[12]={1,1,1,1,1,0,1,1,1,1,0,1};
__constant__ unsigned char sg_w[12]={0,1,2,3,4,5,5,6,7,8,9,9};
__constant__ short sg_wcol[12]={0,0,0,0,0,0,63,0,0,0,0,256};
__constant__ short sg_kmax[12]={63,256,256,256,256,63,256,256,256,256,256,27};
__constant__ short sg_wstr[12]={63,256,256,256,256,319,319,256,256,256,283,283};
__constant__ short sg_nval[12]={256,256,256,256,256,256,256,256,256,256,128,128};

__device__ __align__(1024) unsigned char g_ws[NCHUNK*16384];

struct PrepParams { const float* w[10]; };
__global__ void prep(PrepParams pp){
    int c = blockIdx.x, s = 11;
    for (int i = 1; i < 12; i++) if (c < sg_cum[i]){ s = i-1; break; }
    int ci = c - sg_cum[s];
    const float* W = pp.w[sg_w[s]];
    int kval = sg_kmax[s] - 32*ci; if (kval > 32) kval = 32;
    int nval = sg_nval[s], ws = sg_wstr[s], col0 = sg_wcol[s] + ci*32;
    unsigned char* dst = g_ws + (long long)c*16384;
    for (int idx = threadIdx.x; idx < 8192; idx += blockDim.x){
        int n = idx>>5, kk = idx&31;
        float w = (kk < kval && n < nval) ? W[n*ws + col0 + kk] : 0.f;
        uint32_t off = (uint32_t)((((n>>3)*4 + (kk>>3))<<7) + ((n&7)<<4) + ((kk&7)<<1));
        *(__half*)(dst+off) = __float2half_rn(w);
    }
}

struct MainParams {
    const float* pts; const float* dirs;
    const float* bias[10];           // bb0..7, brm, br0
    const float* Wsig; const float* bsig;
    const float* Wr1;  const float* br1;
    float* out; int N;
};

__device__ __forceinline__ float embed_val(const float* base, int g0, int m, int k){
    if (k < 3) return base[(g0+m)*3+k];
    int q = k-3, f = q/6, rr = q - f*6, d = rr%3;
    float x = base[(g0+m)*3+d] * (float)(1<<f);
    return (rr < 3) ? sinf(x) : cosf(x);
}
__device__ __forceinline__ void store_a(unsigned char* smem, int m, int col, float v){
    uint32_t off = (uint32_t)((((m>>3)*40 + (col>>3))<<7) + (m&7)*16 + (col&7)*2);
    *(__half*)(smem+SM_A+off) = __float2half_rn(v);
}
__device__ __forceinline__ float read_a(const unsigned char* smem, int m, int k){
    uint32_t off = (uint32_t)((((m>>3)*40 + (k>>3))<<7) + (m&7)*16 + (k&7)*2);
    return __half2float(*(const __half*)(smem+SM_A+off));
}

__global__ void __launch_bounds__(256,2) nerf_mma(MainParams P)
{
    extern __shared__ __align__(1024) unsigned char smem[];
    const uint32_t sb = smem_u32(smem), mb = sb + SM_MBAR;
    const int tid = threadIdx.x, lane = tid&31, wid = tid>>5;
    const int ms = wid&1, ns = wid>>1;       // 2 m-blocks x 4 n-blocks
    const int gp0 = blockIdx.x*64;
    const long long N = P.N;

    const uint32_t abase = sb + SM_A +
        (uint32_t)(((ms*4 + ((lane>>3)&1))*40 + (lane>>4))*128 + (lane&7)*16);
    const uint32_t bbase =
        (uint32_t)((ns*8 + (lane>>4))*512 + ((lane>>3)&1)*128 + (lane&7)*16);

    if (tid == 0){
        MB_INIT(mb,1); MB_INIT(mb+8,1); MB_INIT(mb+16,1); MB_INIT(mb+24,1);
        MB_INIT(mb+32,8); MB_INIT(mb+40,8); MB_INIT(mb+48,8); MB_INIT(mb+56,8);
    }
    __syncthreads();
    if (tid == 0){
        #pragma unroll
        for (int b = 0; b < 4; b++){
            MB_EXTX(mb + 8*b, 16384);
            bulk_g2s(sb + SM_W + b*16384, g_ws + (long long)b*16384, 16384, mb + 8*b);
        }
    }
    for (int i = tid*16; i < 40960; i += 256*16) *(uint4*)(smem+i) = make_uint4(0,0,0,0);
    __syncthreads();
    for (int idx = tid; idx < 64*63; idx += 256){
        int m = idx/63, k = idx - m*63;
        store_a(smem, m, 256+k, embed_val(P.pts, gp0, m, k));
    }
    {
        float* outD = P.out + 4*N;
        for (int idx = tid; idx < 64*27; idx += 256){
            int m = idx/27, k = idx - m*27;
            outD[(long long)(gp0+m)*27 + k] = embed_val(P.dirs, gp0, m, k);
        }
    }
    __syncthreads();

    float acc[64];
    int c = 0; uint32_t phs = 0, cphs = 0;
    #pragma unroll 1
    for (int s = 0; s < 12; s++){
        const int cnt = sg_cnt[s], layer = sg_layer[s];
        const bool act = (sg_nval[s] == 256) || (ns < 2);   // skip zero-padded head halves
        uint32_t koff = (uint32_t)sg_akt[s] * 128;
        if (sg_first[s]){
            #pragma unroll
            for (int i = 0; i < 64; i++) acc[i] = 0.f;
        }
        #pragma unroll 1
        for (int ci = 0; ci < cnt; ci++, c++){
            int buf = c & 3;
            MB_WAIT(mb + 8*buf, (phs>>buf)&1);
            phs ^= 1u << buf;
            if (act){
                const uint32_t ka = abase + koff;
                const uint32_t wbb = sb + SM_W + buf*16384 + bbase;
                uint32_t af[4];   // indexed [kh*2+mh], 4 LDMX4 -> 16 regs
                uint32_t afr[4][4];
                LDMX4(afr[0], ka);               // kh0 mh0
                LDMX4(afr[1], ka + 10240);       // kh0 mh1
                LDMX4(afr[2], ka + 256);         // kh1 mh0
                LDMX4(afr[3], ka + 10240 + 256); // kh1 mh1
                (void)af;
                #define af afr
                // software-pipelined B groups: prefetch next while MMAs run
                uint32_t bA[4], bB[4];
                LDMX4(bA, wbb + 0);                        // i0 (kh0,g0)
                LDMX4(bB, wbb + 1024); DOGRP(bA, 0, 0);    // pf i1
                LDMX4(bA, wbb + 2048); DOGRP(bB, 0, 1);    // pf i2
                LDMX4(bB, wbb + 3072); DOGRP(bA, 0, 2);    // pf i3
                LDMX4(bA, wbb + 256);  DOGRP(bB, 0, 3);    // pf i4
                LDMX4(bB, wbb + 1280); DOGRP(bA, 1, 0);    // pf i5
                LDMX4(bA, wbb + 2304); DOGRP(bB, 1, 1);    // pf i6
                LDMX4(bB, wbb + 3328); DOGRP(bA, 1, 2);    // pf i7
                DOGRP(bB, 1, 3);
                #undef af
            }
            koff += 512;
            if (lane == 0) MB_ARR(mb + 32 + 8*buf);
            if (tid == 0 && c+4 < NCHUNK){
                MB_WAIT(mb + 32 + 8*buf, (cphs>>buf)&1);
                cphs ^= 1u << buf;
                MB_EXTX(mb + 8*buf, 16384);
                bulk_g2s(sb + SM_W + buf*16384, g_ws + (long long)(c+4)*16384, 16384, mb + 8*buf);
            }
        }
        if (sg_end[s]){
            __syncthreads();   // all warps done reading A for this layer
            const float* bp = P.bias[layer];
            const int nmax = (layer == 9) ? 128 : 256;
            if (act){
                #pragma unroll
                for (int nti = 0; nti < 8; nti++)
                    #pragma unroll
                    for (int mh = 0; mh < 2; mh++){
                        float* a4 = acc + (nti*2 + mh)*4;
                        int n0 = ns*64 + nti*8 + (lane&3)*2;
                        int mr = ms*32 + mh*16 + (lane>>2);
                        float b0 = (n0 < nmax) ? __ldg(bp + n0) : 0.f;
                        float b1 = (n0+1 < nmax) ? __ldg(bp + n0 + 1) : 0.f;
                        int ktw = ns*8 + nti;
                        float v0 = fmaxf(a4[0]+b0,0.f), v1 = fmaxf(a4[1]+b1,0.f);
                        float v2 = fmaxf(a4[2]+b0,0.f), v3 = fmaxf(a4[3]+b1,0.f);
                        uint32_t o0 = (uint32_t)((((mr>>3)*40 + ktw)<<7) + (mr&7)*16 + (lane&3)*4);
                        int m2 = mr + 8;
                        uint32_t o1 = (uint32_t)((((m2>>3)*40 + ktw)<<7) + (m2&7)*16 + (lane&3)*4);
                        *(uint32_t*)(smem+SM_A+o0) = packh2(v0, v1);
                        *(uint32_t*)(smem+SM_A+o1) = packh2(v2, v3);
                    }
            }
            if (layer == 5){
                for (int idx = tid; idx < 64*27; idx += 256){
                    int m = idx/27, k = idx - m*27;
                    store_a(smem, m, 256+k, embed_val(P.dirs, gp0, m, k));
                }
            }
            __syncthreads();
            if (layer == 7 && tid < 64){
                int m = tid; float ssum = __ldg(P.bsig);
                #pragma unroll 8
                for (int k = 0; k < 256; k++) ssum = fmaf(read_a(smem, m, k), __ldg(P.Wsig + k), ssum);
                P.out[3*N + gp0 + m] = ssum;
            }
            if (layer == 9 && tid < 64){
                int m = tid;
                float r0 = __ldg(P.br1+0), r1 = __ldg(P.br1+1), r2 = __ldg(P.br1+2);
                #pragma unroll 8
                for (int k = 0; k < 128; k++){
                    float av = read_a(smem, m, k);
                    r0 = fmaf(av, __ldg(P.Wr1 + k), r0);
                    r1 = fmaf(av, __ldg(P.Wr1 + 128 + k), r1);
                    r2 = fmaf(av, __ldg(P.Wr1 + 256 + k), r2);
                }
                long long gm = gp0 + m;
                P.out[gm*3+0] = 1.f/(1.f + expf(-r0));
                P.out[gm*3+1] = 1.f/(1.f + expf(-r1));
                P.out[gm*3+2] = 1.f/(1.f + expf(-r2));
            }
        }
    }
}

extern "C" void kernel_launch(void* const* d_in, const int* in_sizes, int n_in,
                              void* d_out, int out_size)
{
    PrepParams pp;
    for (int i = 0; i < 8; i++) pp.w[i] = (const float*)d_in[2 + 2*i];
    pp.w[8] = (const float*)d_in[20];
    pp.w[9] = (const float*)d_in[22];

    MainParams mp;
    mp.pts  = (const float*)d_in[0];
    mp.dirs = (const float*)d_in[1];
    for (int i = 0; i < 8; i++) mp.bias[i] = (const float*)d_in[3 + 2*i];
    mp.bias[8] = (const float*)d_in[21];     // brm
    mp.bias[9] = (const float*)d_in[23];     // br0
    mp.Wsig = (const float*)d_in[18]; mp.bsig = (const float*)d_in[19];
    mp.Wr1  = (const float*)d_in[24]; mp.br1  = (const float*)d_in[25];
    mp.out  = (float*)d_out;
    mp.N    = in_sizes[0] / 3;

    prep<<<NCHUNK, 256>>>(pp);
    cudaFuncSetAttribute(nerf_mma, cudaFuncAttributeMaxDynamicSharedMemorySize, SM_TOTAL);
    nerf_mma<<<mp.N/64, 256, SM_TOTAL>>>(mp);
}